// round 1
// baseline (speedup 1.0000x reference)
#include <cuda_runtime.h>

// Problem constants
#define B_TOT 2048
#define T_LEN 128
#define DIN   64
#define UDIM  128
#define NG    512   // 4*U
#define KTOT  192   // DIN + U
#define BT    16    // batch rows per CTA
#define NTH   512
#define XH_S  20    // padded row stride for [x|h] tile (floats)
#define GS_S  16    // row stride for gate staging (floats)

// Pre-transposed fused weights: g_Wt[k][n], k in [0,192): k<64 -> W_ih, else W_hh
__device__ float g_Wt[KTOT * NG];
__device__ float g_bias[NG];

__global__ void prep_kernel(const float* __restrict__ W_ih, const float* __restrict__ W_hh,
                            const float* __restrict__ b_ih, const float* __restrict__ b_hh) {
    int k = blockIdx.x;
    int n = threadIdx.x;
    g_Wt[k * NG + n] = (k < DIN) ? W_ih[n * DIN + k] : W_hh[n * UDIM + (k - DIN)];
    if (k == 0) g_bias[n] = b_ih[n] + b_hh[n];
}

__device__ __forceinline__ float fsig(float x) {
    return 1.0f / (1.0f + __expf(-x));
}
__device__ __forceinline__ float ftanh(float x) {
    float a = fabsf(x);
    float e = __expf(2.0f * a);
    float r = 1.0f - 2.0f / (1.0f + e);
    return copysignf(r, x);
}

__global__ void __launch_bounds__(NTH, 2)
lstm_kernel(const float* __restrict__ x_st, const float* __restrict__ x_sc,
            const float* __restrict__ bn_gamma, const float* __restrict__ bn_beta,
            const float* __restrict__ bn_mean, const float* __restrict__ bn_var,
            float* __restrict__ out) {
    // sm_xh: [192][XH_S]  rows 0..63 = x_t (transposed, [k][b]), rows 64..191 = h (=[u][b])
    // sm_gs: [512][GS_S]  activated gates, [n][b]
    __shared__ float sm_xh[KTOT * XH_S];
    __shared__ float sm_gs[NG * GS_S];

    const int path  = blockIdx.y;            // 0 = SNN (st), 1 = ANN (sc)
    const int bbase = blockIdx.x * BT;
    const float* __restrict__ xin = (path == 0) ? x_st : x_sc;
    const float* __restrict__ xrow = xin + (size_t)bbase * T_LEN * DIN;

    const int n    = threadIdx.x;            // gate column this thread computes
    const int u    = n & (UDIM - 1);         // state unit this thread owns
    const int gate = n >> 7;                 // 0:i 1:f 2:g 3:o
    const int b0   = gate * 4;               // this thread owns batch rows b0..b0+3 of state

    // zero the whole [x|h] tile (h starts at 0, pads stay 0)
    for (int i = n; i < KTOT * XH_S; i += NTH) sm_xh[i] = 0.0f;

    float c[4], m[4], s[4];
#pragma unroll
    for (int j = 0; j < 4; j++) { c[j] = 0.0f; m[j] = 0.0f; s[j] = 0.0f; }

    const float bias = g_bias[n];
    const float* __restrict__ Wp = g_Wt + n;

    for (int t = 0; t < T_LEN; t++) {
        // ---- load x_t (16 rows x 64 cols), transposed into sm_xh[k][b] ----
        {
            int e = n;                        // 0..511
            int b = e >> 6, k = e & 63;
            sm_xh[k * XH_S + b] = xrow[((size_t)b * T_LEN + t) * DIN + k];
            e = n + NTH;                      // 512..1023
            b = e >> 6; k = e & 63;
            sm_xh[k * XH_S + b] = xrow[((size_t)b * T_LEN + t) * DIN + k];
        }
        __syncthreads();   // (A) x_t and previous step's h visible

        // ---- gates[b][n] = sum_k xh[k][b] * Wt[k][n] + bias ----
        float acc[16];
#pragma unroll
        for (int j = 0; j < 16; j++) acc[j] = bias;

#pragma unroll 2
        for (int k = 0; k < KTOT; k++) {
            float w = __ldg(Wp + k * NG);                    // coalesced, L2-hot
            const float4* xr = (const float4*)(sm_xh + k * XH_S);  // broadcast
            float4 a0 = xr[0], a1 = xr[1], a2 = xr[2], a3 = xr[3];
            acc[0]  = fmaf(w, a0.x, acc[0]);
            acc[1]  = fmaf(w, a0.y, acc[1]);
            acc[2]  = fmaf(w, a0.z, acc[2]);
            acc[3]  = fmaf(w, a0.w, acc[3]);
            acc[4]  = fmaf(w, a1.x, acc[4]);
            acc[5]  = fmaf(w, a1.y, acc[5]);
            acc[6]  = fmaf(w, a1.z, acc[6]);
            acc[7]  = fmaf(w, a1.w, acc[7]);
            acc[8]  = fmaf(w, a2.x, acc[8]);
            acc[9]  = fmaf(w, a2.y, acc[9]);
            acc[10] = fmaf(w, a2.z, acc[10]);
            acc[11] = fmaf(w, a2.w, acc[11]);
            acc[12] = fmaf(w, a3.x, acc[12]);
            acc[13] = fmaf(w, a3.y, acc[13]);
            acc[14] = fmaf(w, a3.z, acc[14]);
            acc[15] = fmaf(w, a3.w, acc[15]);
        }

        // ---- activations, stage to smem ----
        float va[16];
        if (gate == 2) {
#pragma unroll
            for (int j = 0; j < 16; j++) va[j] = ftanh(acc[j]);
        } else {
#pragma unroll
            for (int j = 0; j < 16; j++) va[j] = fsig(acc[j]);
        }
        float4* gw = (float4*)(sm_gs + n * GS_S);
        gw[0] = make_float4(va[0],  va[1],  va[2],  va[3]);
        gw[1] = make_float4(va[4],  va[5],  va[6],  va[7]);
        gw[2] = make_float4(va[8],  va[9],  va[10], va[11]);
        gw[3] = make_float4(va[12], va[13], va[14], va[15]);
        __syncthreads();   // (B) all gates visible

        // ---- state update: thread owns (u, b0..b0+3) ----
        float4 iv = *(const float4*)(sm_gs + (0 * UDIM + u) * GS_S + b0);
        float4 fv = *(const float4*)(sm_gs + (1 * UDIM + u) * GS_S + b0);
        float4 gv = *(const float4*)(sm_gs + (2 * UDIM + u) * GS_S + b0);
        float4 ov = *(const float4*)(sm_gs + (3 * UDIM + u) * GS_S + b0);
        float ia[4] = {iv.x, iv.y, iv.z, iv.w};
        float fa[4] = {fv.x, fv.y, fv.z, fv.w};
        float ga[4] = {gv.x, gv.y, gv.z, gv.w};
        float oa[4] = {ov.x, ov.y, ov.z, ov.w};
        float hv[4];
        if (path) {        // ANN: h = o * tanh(c)
#pragma unroll
            for (int j = 0; j < 4; j++) {
                c[j] = fa[j] * c[j] + ia[j] * ga[j];
                hv[j] = oa[j] * ftanh(c[j]);
                s[j] += hv[j];
            }
        } else {           // SNN: integrate-and-fire, spikes feed back as h
#pragma unroll
            for (int j = 0; j < 4; j++) {
                c[j] = fa[j] * c[j] + ia[j] * ga[j];
                m[j] += oa[j] * ftanh(c[j]);
                float spk = (m[j] >= 1.0f) ? 1.0f : 0.0f;
                m[j] -= spk;
                hv[j] = spk;
                s[j] += spk;
            }
        }
        float* hw = sm_xh + (DIN + u) * XH_S + b0;
        hw[0] = hv[0]; hw[1] = hv[1]; hw[2] = hv[2]; hw[3] = hv[3];
        // no barrier needed here: next iteration's barrier (A) orders these
        // h-writes and gs-reads against the next step's gemm/gs-writes.
    }

    // ---- epilogue: temporal mean + BatchNorm (eval mode) ----
    float scale = bn_gamma[u] * rsqrtf(bn_var[u] + 1e-5f);
    float shift = bn_beta[u] - bn_mean[u] * scale;
    const float inv = 1.0f / (float)T_LEN;
    size_t ob = ((size_t)path * B_TOT + bbase + b0) * UDIM + u;
#pragma unroll
    for (int j = 0; j < 4; j++) {
        out[ob + (size_t)j * UDIM] = s[j] * inv * scale + shift;
    }
}

extern "C" void kernel_launch(void* const* d_in, const int* in_sizes, int n_in,
                              void* d_out, int out_size) {
    const float* x_st  = (const float*)d_in[0];
    const float* x_sc  = (const float*)d_in[1];
    const float* W_ih  = (const float*)d_in[2];
    const float* W_hh  = (const float*)d_in[3];
    const float* b_ih  = (const float*)d_in[4];
    const float* b_hh  = (const float*)d_in[5];
    const float* gamma = (const float*)d_in[6];
    const float* beta  = (const float*)d_in[7];
    const float* mean  = (const float*)d_in[8];
    const float* var   = (const float*)d_in[9];

    prep_kernel<<<KTOT, NG>>>(W_ih, W_hh, b_ih, b_hh);

    dim3 grid(B_TOT / BT, 2);
    lstm_kernel<<<grid, NTH>>>(x_st, x_sc, gamma, beta, mean, var, (float*)d_out);
}

// round 3
// speedup vs baseline: 1.1413x; 1.1413x over previous
#include <cuda_runtime.h>

// Problem constants
#define B_TOT 2048
#define T_LEN 128
#define DIN   64
#define UDIM  128
#define NG    512   // 4*U
#define KTOT  192   // DIN + U
#define BT    16    // batch rows per CTA
#define NTH   512
#define XH_S  20    // padded row stride for [x|h] tile (floats)
#define GS_S  20    // padded row stride for gate staging (floats): 4-way instead of 16-way conflicts
#define KUF   4     // weight prefetch block

#define SMEM_XH_FLOATS (KTOT * XH_S)             // 3840
#define SMEM_GS_FLOATS (NG * GS_S)               // 10240
#define SMEM_TOTAL_BYTES ((SMEM_XH_FLOATS + SMEM_GS_FLOATS) * 4)  // 56320

// Pre-transposed fused weights: g_Wt[k][n], k in [0,192): k<64 -> W_ih, else W_hh
__device__ float g_Wt[KTOT * NG];
__device__ float g_bias[NG];

__global__ void prep_kernel(const float* __restrict__ W_ih, const float* __restrict__ W_hh,
                            const float* __restrict__ b_ih, const float* __restrict__ b_hh) {
    int k = blockIdx.x;
    int n = threadIdx.x;
    g_Wt[k * NG + n] = (k < DIN) ? W_ih[n * DIN + k] : W_hh[n * UDIM + (k - DIN)];
    if (k == 0) g_bias[n] = b_ih[n] + b_hh[n];
}

__device__ __forceinline__ float fsig(float x) {
    return 1.0f / (1.0f + __expf(-x));
}
__device__ __forceinline__ float ftanh(float x) {
    float a = fabsf(x);
    float e = __expf(2.0f * a);
    float r = 1.0f - 2.0f / (1.0f + e);
    return copysignf(r, x);
}

// packed fp32x2 FMA (sm_100a): d = a*b + d  (same fp32 RN rounding as FFMA)
#define FFMA2(d, a, b) \
    asm("fma.rn.f32x2 %0, %1, %2, %0;" : "+l"(d) : "l"(a), "l"(b))

__device__ __forceinline__ unsigned long long splat2(float w) {
    unsigned long long r;
    asm("mov.b64 %0, {%1, %1};" : "=l"(r) : "f"(w));
    return r;
}
__device__ __forceinline__ void unpack2(unsigned long long p, float& lo, float& hi) {
    asm("mov.b64 {%0, %1}, %2;" : "=f"(lo), "=f"(hi) : "l"(p));
}

__global__ void __launch_bounds__(NTH, 2)
lstm_kernel(const float* __restrict__ x_st, const float* __restrict__ x_sc,
            const float* __restrict__ bn_gamma, const float* __restrict__ bn_beta,
            const float* __restrict__ bn_mean, const float* __restrict__ bn_var,
            float* __restrict__ out) {
    // dynamic smem:
    //   sm_xh: [192][XH_S]  rows 0..63 = x_t (transposed, [k][b]), rows 64..191 = h ([u][b])
    //   sm_gs: [512][GS_S]  activated gates, [n][b]
    extern __shared__ float smem[];
    float* sm_xh = smem;
    float* sm_gs = smem + SMEM_XH_FLOATS;

    const int path  = blockIdx.y;            // 0 = SNN (st), 1 = ANN (sc)
    const int bbase = blockIdx.x * BT;
    const float* __restrict__ xin = (path == 0) ? x_st : x_sc;
    const float* __restrict__ xrow = xin + (size_t)bbase * T_LEN * DIN;

    const int n    = threadIdx.x;            // gate column this thread computes
    const int u    = n & (UDIM - 1);         // state unit this thread owns
    const int gate = n >> 7;                 // 0:i 1:f 2:g 3:o
    const int b0   = gate * 4;               // this thread owns batch rows b0..b0+3 of state

    // x staging: thread handles elements n and n+512 of the 1024-elem x tile
    const int xb0 = n >> 6, xk0 = n & 63;          // element n
    const int xb1 = (n + NTH) >> 6, xk1 = n & 63;  // element n+512 (same k, b+8)

    // zero the whole [x|h] tile (h starts at 0, pads stay 0)
    for (int i = n; i < SMEM_XH_FLOATS; i += NTH) sm_xh[i] = 0.0f;

    float c[4], m[4], s[4];
#pragma unroll
    for (int j = 0; j < 4; j++) { c[j] = 0.0f; m[j] = 0.0f; s[j] = 0.0f; }

    const float bias = g_bias[n];
    const unsigned long long biasp = splat2(bias);
    const float* __restrict__ Wp = g_Wt + n;

    // preload x_0 into regs and stage it (pre-barrier, so no race)
    float rx0 = xrow[((size_t)xb0 * T_LEN + 0) * DIN + xk0];
    float rx1 = xrow[((size_t)xb1 * T_LEN + 0) * DIN + xk1];
    sm_xh[xk0 * XH_S + xb0] = rx0;
    sm_xh[xk1 * XH_S + xb1] = rx1;

    for (int t = 0; t < T_LEN; t++) {
        __syncthreads();   // (A) x_t and h_t visible to everyone

        // issue next step's x loads early; consumed after barrier (B)
        if (t + 1 < T_LEN) {
            rx0 = xrow[((size_t)xb0 * T_LEN + (t + 1)) * DIN + xk0];
            rx1 = xrow[((size_t)xb1 * T_LEN + (t + 1)) * DIN + xk1];
        }

        // ---- gates[b][n] = sum_k xh[k][b] * Wt[k][n] + bias (packed f32x2) ----
        unsigned long long acc[8];
#pragma unroll
        for (int j = 0; j < 8; j++) acc[j] = biasp;

        float w[KUF], wn[KUF];
#pragma unroll
        for (int i = 0; i < KUF; i++) w[i] = __ldg(Wp + i * NG);

        for (int kb = 0; kb < KTOT; kb += KUF) {
            if (kb + KUF < KTOT) {
#pragma unroll
                for (int i = 0; i < KUF; i++) wn[i] = __ldg(Wp + (kb + KUF + i) * NG);
            }
#pragma unroll
            for (int i = 0; i < KUF; i++) {
                unsigned long long wp = splat2(w[i]);
                const ulonglong2* xr = (const ulonglong2*)(sm_xh + (kb + i) * XH_S);
                ulonglong2 p0 = xr[0];   // batch pairs (0,1),(2,3)
                ulonglong2 p1 = xr[1];   // (4,5),(6,7)
                ulonglong2 p2 = xr[2];   // (8,9),(10,11)
                ulonglong2 p3 = xr[3];   // (12,13),(14,15)
                FFMA2(acc[0], p0.x, wp);
                FFMA2(acc[1], p0.y, wp);
                FFMA2(acc[2], p1.x, wp);
                FFMA2(acc[3], p1.y, wp);
                FFMA2(acc[4], p2.x, wp);
                FFMA2(acc[5], p2.y, wp);
                FFMA2(acc[6], p3.x, wp);
                FFMA2(acc[7], p3.y, wp);
            }
#pragma unroll
            for (int i = 0; i < KUF; i++) w[i] = wn[i];
        }

        // ---- activations, stage to smem ----
        float va[16];
#pragma unroll
        for (int j = 0; j < 8; j++) unpack2(acc[j], va[2 * j], va[2 * j + 1]);
        if (gate == 2) {
#pragma unroll
            for (int j = 0; j < 16; j++) va[j] = ftanh(va[j]);
        } else {
#pragma unroll
            for (int j = 0; j < 16; j++) va[j] = fsig(va[j]);
        }
        float4* gw = (float4*)(sm_gs + n * GS_S);
        gw[0] = make_float4(va[0],  va[1],  va[2],  va[3]);
        gw[1] = make_float4(va[4],  va[5],  va[6],  va[7]);
        gw[2] = make_float4(va[8],  va[9],  va[10], va[11]);
        gw[3] = make_float4(va[12], va[13], va[14], va[15]);
        __syncthreads();   // (B) all gates visible; all gemm reads of sm_xh done

        // ---- stage next x_t (safe now: gemm reads finished) ----
        if (t + 1 < T_LEN) {
            sm_xh[xk0 * XH_S + xb0] = rx0;
            sm_xh[xk1 * XH_S + xb1] = rx1;
        }

        // ---- state update: thread owns (u, b0..b0+3) ----
        float4 iv = *(const float4*)(sm_gs + (0 * UDIM + u) * GS_S + b0);
        float4 fv = *(const float4*)(sm_gs + (1 * UDIM + u) * GS_S + b0);
        float4 gv = *(const float4*)(sm_gs + (2 * UDIM + u) * GS_S + b0);
        float4 ov = *(const float4*)(sm_gs + (3 * UDIM + u) * GS_S + b0);
        float ia[4] = {iv.x, iv.y, iv.z, iv.w};
        float fa[4] = {fv.x, fv.y, fv.z, fv.w};
        float ga[4] = {gv.x, gv.y, gv.z, gv.w};
        float oa[4] = {ov.x, ov.y, ov.z, ov.w};
        float hv[4];
        if (path) {        // ANN: h = o * tanh(c)
#pragma unroll
            for (int j = 0; j < 4; j++) {
                c[j] = fa[j] * c[j] + ia[j] * ga[j];
                hv[j] = oa[j] * ftanh(c[j]);
                s[j] += hv[j];
            }
        } else {           // SNN: integrate-and-fire, spikes feed back as h
#pragma unroll
            for (int j = 0; j < 4; j++) {
                c[j] = fa[j] * c[j] + ia[j] * ga[j];
                m[j] += oa[j] * ftanh(c[j]);
                float spk = (m[j] >= 1.0f) ? 1.0f : 0.0f;
                m[j] -= spk;
                hv[j] = spk;
                s[j] += spk;
            }
        }
        float* hw = sm_xh + (DIN + u) * XH_S + b0;
        hw[0] = hv[0]; hw[1] = hv[1]; hw[2] = hv[2]; hw[3] = hv[3];
        // next iteration's barrier (A) orders these writes before the next gemm
    }

    // ---- epilogue: temporal mean + BatchNorm (eval mode) ----
    float scale = bn_gamma[u] * rsqrtf(bn_var[u] + 1e-5f);
    float shift = bn_beta[u] - bn_mean[u] * scale;
    const float inv = 1.0f / (float)T_LEN;
    size_t ob = ((size_t)path * B_TOT + bbase + b0) * UDIM + u;
#pragma unroll
    for (int j = 0; j < 4; j++) {
        out[ob + (size_t)j * UDIM] = s[j] * inv * scale + shift;
    }
}

extern "C" void kernel_launch(void* const* d_in, const int* in_sizes, int n_in,
                              void* d_out, int out_size) {
    const float* x_st  = (const float*)d_in[0];
    const float* x_sc  = (const float*)d_in[1];
    const float* W_ih  = (const float*)d_in[2];
    const float* W_hh  = (const float*)d_in[3];
    const float* b_ih  = (const float*)d_in[4];
    const float* b_hh  = (const float*)d_in[5];
    const float* gamma = (const float*)d_in[6];
    const float* beta  = (const float*)d_in[7];
    const float* mean  = (const float*)d_in[8];
    const float* var   = (const float*)d_in[9];

    // raise dynamic smem limit (idempotent; legal during graph capture — not a stream op)
    cudaFuncSetAttribute(lstm_kernel, cudaFuncAttributeMaxDynamicSharedMemorySize,
                         SMEM_TOTAL_BYTES);

    prep_kernel<<<KTOT, NG>>>(W_ih, W_hh, b_ih, b_hh);

    dim3 grid(B_TOT / BT, 2);
    lstm_kernel<<<grid, NTH, SMEM_TOTAL_BYTES>>>(x_st, x_sc, gamma, beta, mean, var,
                                                 (float*)d_out);
}